// round 1
// baseline (speedup 1.0000x reference)
#include <cuda_runtime.h>
#include <math.h>

#define NB 512
#define NT 256
#define NC 384
#define NH 64
#define NS 256   // BS == T

// scratch: per row n=b*T+t: [0:64)=q, [64:128)=k, [128:192)=v
__device__ __align__(16) float g_qkv[NB * NT * 192];

// ---------------- Kernel 1: fused QKV projection ----------------
// GEMM [131072 x 384] x [384 x 192], BM=64, BN=192, BK=16, 256 thr, 4x12 tile
__global__ __launch_bounds__(256) void qkv_proj_kernel(
    const float* __restrict__ x,
    const float* __restrict__ Wq,
    const float* __restrict__ Wk,
    const float* __restrict__ Wv)
{
    __shared__ float As[16][68];    // A^T tile: As[k][m]
    __shared__ float Bs[16][200];   // B tile:   Bs[k][n], n in [0,192)

    const int m0  = blockIdx.x * 64;
    const int tid = threadIdx.x;
    const int tr  = tid >> 4;   // 0..15 -> rows tr*4..tr*4+3
    const int tc  = tid & 15;   // 0..15 -> cols tc*12..tc*12+11

    float acc[4][12];
#pragma unroll
    for (int i = 0; i < 4; i++)
#pragma unroll
        for (int j = 0; j < 12; j++) acc[i][j] = 0.f;

    const int arow = tid >> 2;  // 0..63
    const int aseg = tid & 3;   // 0..3

    for (int k0 = 0; k0 < NC; k0 += 16) {
        // A tile 64x16, transposed store
        float4 av = *(const float4*)&x[(m0 + arow) * NC + k0 + aseg * 4];
        As[aseg * 4 + 0][arow] = av.x;
        As[aseg * 4 + 1][arow] = av.y;
        As[aseg * 4 + 2][arow] = av.z;
        As[aseg * 4 + 3][arow] = av.w;
        // B tile 16x192 (q|k|v columns)
#pragma unroll
        for (int r = 0; r < 3; r++) {
            int L    = tid + 256 * r;      // 0..767
            int krow = L / 48;
            int w    = L % 48;
            int seg  = w >> 4;             // 0:Wq 1:Wk 2:Wv
            int off  = w & 15;
            const float* Wsel = (seg == 0) ? Wq : (seg == 1) ? Wk : Wv;
            float4 bv = *(const float4*)&Wsel[(k0 + krow) * NH + off * 4];
            *(float4*)&Bs[krow][seg * 64 + off * 4] = bv;
        }
        __syncthreads();
#pragma unroll
        for (int kk = 0; kk < 16; kk++) {
            float4 a  = *(const float4*)&As[kk][tr * 4];
            float4 b0 = *(const float4*)&Bs[kk][tc * 12];
            float4 b1 = *(const float4*)&Bs[kk][tc * 12 + 4];
            float4 b2 = *(const float4*)&Bs[kk][tc * 12 + 8];
            float am[4]  = {a.x, a.y, a.z, a.w};
            float bm[12] = {b0.x, b0.y, b0.z, b0.w,
                            b1.x, b1.y, b1.z, b1.w,
                            b2.x, b2.y, b2.z, b2.w};
#pragma unroll
            for (int i = 0; i < 4; i++)
#pragma unroll
                for (int j = 0; j < 12; j++)
                    acc[i][j] = fmaf(am[i], bm[j], acc[i][j]);
        }
        __syncthreads();
    }
#pragma unroll
    for (int i = 0; i < 4; i++) {
        int row    = m0 + tr * 4 + i;
        float* dst = &g_qkv[row * 192 + tc * 12];
        *(float4*)&dst[0] = make_float4(acc[i][0], acc[i][1], acc[i][2],  acc[i][3]);
        *(float4*)&dst[4] = make_float4(acc[i][4], acc[i][5], acc[i][6],  acc[i][7]);
        *(float4*)&dst[8] = make_float4(acc[i][8], acc[i][9], acc[i][10], acc[i][11]);
    }
}

// ---------------- Kernel 2: fused score/softmax/value ----------------
// One block per (b, t-block of 64). SLIM = t0 + 64 (causal s-range).
template <int SLIM>
__device__ __forceinline__ void attn_body(
    const float* __restrict__ Wql,
    const float* __restrict__ Wkl,
    float* __restrict__ out,
    int b, int tb)
{
    constexpr int US = SLIM + 8;       // padded row stride (mult of 4)
    constexpr int CW = SLIM / 16;      // cols per thread in GEMM1
    extern __shared__ float smem[];
    float* sU = smem;                  // 64 * US   : scores -> probs
    float* sW = sU + 64 * US;          // 16 * US   : Wcat k-chunk
    float* sZ = sW + 16 * US;          // 64 * 132  : z = [q|k] rows
    float* sV = sZ + 64 * 132;         // SLIM * 72 : v rows

    const int tid = threadIdx.x;
    const int tr  = tid >> 4;          // 0..15
    const int tc  = tid & 15;          // 0..15
    const int base_row = b * NT + tb * 64;

    // load z: 64 rows x 128 (q|k are first 128 floats of qkv row)
    for (int L = tid; L < 64 * 32; L += 256) {
        int t = L >> 5, f = L & 31;
        float4 v = *(const float4*)&g_qkv[(base_row + t) * 192 + f * 4];
        *(float4*)&sZ[t * 132 + f * 4] = v;
    }
    // load v: SLIM rows x 64
    for (int L = tid; L < SLIM * 16; L += 256) {
        int s = L >> 4, f = L & 15;
        float4 v = *(const float4*)&g_qkv[(b * NT + s) * 192 + 128 + f * 4];
        *(float4*)&sV[s * 72 + f * 4] = v;
    }

    // GEMM1: u[64][SLIM] = z[64][128] @ Wcat[128][SLIM]
    float acc[4][CW];
#pragma unroll
    for (int i = 0; i < 4; i++)
#pragma unroll
        for (int j = 0; j < CW; j++) acc[i][j] = 0.f;

    for (int kt = 0; kt < 8; kt++) {
        const int k0 = kt * 16;
        __syncthreads();               // prev compute done (also covers z/v loads)
        for (int L = tid; L < 4 * SLIM; L += 256) {
            int kr = L / (SLIM / 4);
            int f  = L % (SLIM / 4);
            int kg = k0 + kr;
            const float* Wp = (kg < 64) ? (Wql + kg * NS) : (Wkl + (kg - 64) * NS);
            float4 v = *(const float4*)&Wp[f * 4];
            *(float4*)&sW[kr * US + f * 4] = v;
        }
        __syncthreads();
#pragma unroll
        for (int kk = 0; kk < 16; kk++) {
            float a[4];
#pragma unroll
            for (int i = 0; i < 4; i++) a[i] = sZ[(tr * 4 + i) * 132 + k0 + kk];
            float bm[CW];
#pragma unroll
            for (int u = 0; u < CW / 4; u++) {
                float4 bv = *(const float4*)&sW[kk * US + tc * CW + u * 4];
                bm[u * 4 + 0] = bv.x; bm[u * 4 + 1] = bv.y;
                bm[u * 4 + 2] = bv.z; bm[u * 4 + 3] = bv.w;
            }
#pragma unroll
            for (int i = 0; i < 4; i++)
#pragma unroll
                for (int j = 0; j < CW; j++)
                    acc[i][j] = fmaf(a[i], bm[j], acc[i][j]);
        }
    }

    // tanh + causal mask -> sU
#pragma unroll
    for (int i = 0; i < 4; i++) {
        int tg = tb * 64 + tr * 4 + i;
#pragma unroll
        for (int j = 0; j < CW; j++) {
            int s = tc * CW + j;
            sU[(tr * 4 + i) * US + s] = (s <= tg) ? tanhf(acc[i][j]) : -1e30f;
        }
    }
    __syncthreads();

    // softmax: warp per row group (8 rows per warp)
    {
        const int warp = tid >> 5, lane = tid & 31;
        constexpr int NITER = SLIM / 32;
        for (int rr = 0; rr < 8; rr++) {
            int row = warp * 8 + rr;
            float vals[NITER];
            float m = -1e30f;
#pragma unroll
            for (int q = 0; q < NITER; q++) {
                vals[q] = sU[row * US + q * 32 + lane];
                m = fmaxf(m, vals[q]);
            }
#pragma unroll
            for (int off = 16; off > 0; off >>= 1)
                m = fmaxf(m, __shfl_xor_sync(0xffffffffu, m, off));
            float ssum = 0.f;
#pragma unroll
            for (int q = 0; q < NITER; q++) { vals[q] = __expf(vals[q] - m); ssum += vals[q]; }
#pragma unroll
            for (int off = 16; off > 0; off >>= 1)
                ssum += __shfl_xor_sync(0xffffffffu, ssum, off);
            float inv = 1.f / ssum;
#pragma unroll
            for (int q = 0; q < NITER; q++)
                sU[row * US + q * 32 + lane] = vals[q] * inv;
        }
    }
    __syncthreads();

    // GEMM2: out[64][64] = p[64][SLIM] @ v[SLIM][64]
    float acc2[4][4];
#pragma unroll
    for (int i = 0; i < 4; i++)
#pragma unroll
        for (int j = 0; j < 4; j++) acc2[i][j] = 0.f;

    for (int s = 0; s < SLIM; s += 4) {
        float4 af[4];
#pragma unroll
        for (int i = 0; i < 4; i++)
            af[i] = *(const float4*)&sU[(tr * 4 + i) * US + s];
#pragma unroll
        for (int ss = 0; ss < 4; ss++) {
            float4 bv = *(const float4*)&sV[(s + ss) * 72 + tc * 4];
#pragma unroll
            for (int i = 0; i < 4; i++) {
                float a = ((const float*)&af[i])[ss];
                acc2[i][0] = fmaf(a, bv.x, acc2[i][0]);
                acc2[i][1] = fmaf(a, bv.y, acc2[i][1]);
                acc2[i][2] = fmaf(a, bv.z, acc2[i][2]);
                acc2[i][3] = fmaf(a, bv.w, acc2[i][3]);
            }
        }
    }
#pragma unroll
    for (int i = 0; i < 4; i++) {
        int tg = tb * 64 + tr * 4 + i;
        *(float4*)&out[(b * NT + tg) * NH + tc * 4] =
            make_float4(acc2[i][0], acc2[i][1], acc2[i][2], acc2[i][3]);
    }
}

__global__ __launch_bounds__(256) void attn_kernel(
    const float* __restrict__ Wql,
    const float* __restrict__ Wkl,
    float* __restrict__ out)
{
    const int tb = blockIdx.x;
    const int b  = blockIdx.y;
    if (tb == 0)      attn_body<64 >(Wql, Wkl, out, b, 0);
    else if (tb == 1) attn_body<128>(Wql, Wkl, out, b, 1);
    else if (tb == 2) attn_body<192>(Wql, Wkl, out, b, 2);
    else              attn_body<256>(Wql, Wkl, out, b, 3);
}

// max dynamic smem (SLIM=256): (64*264 + 16*264 + 64*132 + 256*72)*4 = 192000 B
#define ATTN_SMEM_BYTES 192000

extern "C" void kernel_launch(void* const* d_in, const int* in_sizes, int n_in,
                              void* d_out, int out_size)
{
    (void)in_sizes; (void)n_in; (void)out_size;
    const float* x   = (const float*)d_in[0];
    const float* Wq  = (const float*)d_in[1];
    const float* Wk  = (const float*)d_in[2];
    const float* Wv  = (const float*)d_in[3];
    const float* Wql = (const float*)d_in[4];
    const float* Wkl = (const float*)d_in[5];
    float* out = (float*)d_out;

    cudaFuncSetAttribute((const void*)attn_kernel,
                         cudaFuncAttributeMaxDynamicSharedMemorySize,
                         ATTN_SMEM_BYTES);

    qkv_proj_kernel<<<(NB * NT) / 64, 256>>>(x, Wq, Wk, Wv);

    dim3 grid(4, NB);
    attn_kernel<<<grid, 256, ATTN_SMEM_BYTES>>>(Wql, Wkl, out);
}

// round 3
// speedup vs baseline: 1.3222x; 1.3222x over previous
#include <cuda_runtime.h>
#include <cuda_bf16.h>
#include <math.h>
#include <stdint.h>

#define NB 512
#define NT 256
#define NC 384
#define NH 64
#define NS 256
#define NM (NB*NT)   // 131072 rows
#define NN 192       // q|k|v fused output cols

// scratch (device globals: allocation-guard safe)
__device__ __align__(16) float         g_qkv[NM * NN]; // per row: [0:64)=q [64:128)=k [128:192)=v
__device__ __align__(16) __nv_bfloat16 g_wh[NN * NC];  // [n][k] K-major
__device__ __align__(16) __nv_bfloat16 g_wl[NN * NC];

// ---------------- W split-bf16 conversion (tiny) ----------------
__global__ __launch_bounds__(256) void convert_w_kernel(
    const float* __restrict__ Wq, const float* __restrict__ Wk, const float* __restrict__ Wv)
{
    const int idx = blockIdx.x * 256 + threadIdx.x;
    if (idx >= NN * NC) return;
    const int n = idx / NC, k = idx % NC;
    const float* W = (n < 64) ? Wq : (n < 128) ? Wk : Wv;
    float v = W[k * NH + (n & 63)];
    __nv_bfloat16 h = __float2bfloat16(v);
    g_wh[idx] = h;
    g_wl[idx] = __float2bfloat16(v - __bfloat162float(h));
}

// ---------------- mma.sync helpers (baseline PTX ISA, no 'a' target) ----------------
#define LDSM_X4(r, addr)                                                        \
    asm volatile("ldmatrix.sync.aligned.m8n8.x4.shared.b16 {%0,%1,%2,%3}, [%4];" \
        : "=r"((r)[0]), "=r"((r)[1]), "=r"((r)[2]), "=r"((r)[3]) : "r"(addr))

#define LDSM_X2(r, addr)                                                        \
    asm volatile("ldmatrix.sync.aligned.m8n8.x2.shared.b16 {%0,%1}, [%2];"      \
        : "=r"((r)[0]), "=r"((r)[1]) : "r"(addr))

#define MMA_BF16(d, a, b)                                                       \
    asm volatile("mma.sync.aligned.m16n8k16.row.col.f32.bf16.bf16.f32 "         \
        "{%0,%1,%2,%3}, {%4,%5,%6,%7}, {%8,%9}, {%0,%1,%2,%3};"                 \
        : "+f"((d)[0]), "+f"((d)[1]), "+f"((d)[2]), "+f"((d)[3])                \
        : "r"((a)[0]), "r"((a)[1]), "r"((a)[2]), "r"((a)[3]),                   \
          "r"((b)[0]), "r"((b)[1]))

// ---------------- Kernel 1: split-bf16 QKV GEMM via mma.sync ----------------
// D[128,192] per CTA, K=384 in 32-chunks. acc += xh*wh + xl*wh + xh*wl.
// smem (bf16 units, stride 40 per row): XH[128][40] XL[128][40] WH[192][40] WL[192][40]
#define QKV_SMEM_BYTES ((5120 + 5120 + 7680 + 7680) * 2)

__global__ __launch_bounds__(256) void qkv_mma_kernel(const float* __restrict__ x)
{
    extern __shared__ __nv_bfloat16 sm[];
    __nv_bfloat16* sXH = sm;
    __nv_bfloat16* sXL = sm + 5120;
    __nv_bfloat16* sWH = sm + 10240;
    __nv_bfloat16* sWL = sm + 17920;

    const int tid  = threadIdx.x;
    const int lane = tid & 31;
    const int w    = tid >> 5;
    const int wr   = w >> 2;      // 0..1 -> rows wr*64
    const int wc   = w & 3;       // 0..3 -> cols wc*48
    const int m0   = blockIdx.x * 128;

    float acc[4][6][4];
#pragma unroll
    for (int mi = 0; mi < 4; mi++)
#pragma unroll
        for (int ni = 0; ni < 6; ni++)
#pragma unroll
            for (int q = 0; q < 4; q++) acc[mi][ni][q] = 0.f;

    // ldmatrix per-lane offsets
    const int a_row = (lane & 7) + ((lane >> 3) & 1) * 8;  // + tile base row
    const int a_col = (lane >> 4) * 8;                     // + k0
    const int b_n   = lane & 7;                            // + n base (lanes 0-15 used)
    const int b_k   = ((lane >> 3) & 1) * 8;               // + k0

    for (int c = 0; c < 12; c++) {
        const int kc = c * 32;
        __syncthreads();   // previous chunk's ldmatrix done before overwrite

        // stage x chunk: load fp32, split into hi/lo bf16 inline
#pragma unroll
        for (int i = 0; i < 4; i++) {
            int idx = tid + 256 * i;
            int row = idx >> 3, seg = idx & 7;
            float4 v = *(const float4*)&x[(size_t)(m0 + row) * NC + kc + seg * 4];
            float vv[4] = {v.x, v.y, v.z, v.w};
            __nv_bfloat16 h[4], l[4];
#pragma unroll
            for (int j = 0; j < 4; j++) {
                h[j] = __float2bfloat16(vv[j]);
                l[j] = __float2bfloat16(vv[j] - __bfloat162float(h[j]));
            }
            *(uint2*)&sXH[row * 40 + seg * 4] = *(uint2*)h;
            *(uint2*)&sXL[row * 40 + seg * 4] = *(uint2*)l;
        }
        // stage W chunk (already bf16, K-major)
#pragma unroll
        for (int i = 0; i < 3; i++) {
            int idx = tid + 256 * i;
            int row = idx >> 2, seg = idx & 3;
            *(uint4*)&sWH[row * 40 + seg * 8] =
                *(const uint4*)&g_wh[(size_t)row * NC + kc + seg * 8];
            *(uint4*)&sWL[row * 40 + seg * 8] =
                *(const uint4*)&g_wl[(size_t)row * NC + kc + seg * 8];
        }
        __syncthreads();

#pragma unroll
        for (int kk = 0; kk < 2; kk++) {
            const int k0 = kk * 16;
            uint32_t ah[4][4], al[4][4], bh[6][2], bl[6][2];
#pragma unroll
            for (int mi = 0; mi < 4; mi++) {
                uint32_t adh = (uint32_t)__cvta_generic_to_shared(
                    &sXH[(wr * 64 + mi * 16 + a_row) * 40 + k0 + a_col]);
                LDSM_X4(ah[mi], adh);
                uint32_t adl = (uint32_t)__cvta_generic_to_shared(
                    &sXL[(wr * 64 + mi * 16 + a_row) * 40 + k0 + a_col]);
                LDSM_X4(al[mi], adl);
            }
#pragma unroll
            for (int ni = 0; ni < 6; ni++) {
                uint32_t adb = (uint32_t)__cvta_generic_to_shared(
                    &sWH[(wc * 48 + ni * 8 + b_n) * 40 + k0 + b_k]);
                LDSM_X2(bh[ni], adb);
            }
#pragma unroll
            for (int mi = 0; mi < 4; mi++)
#pragma unroll
                for (int ni = 0; ni < 6; ni++) {
                    MMA_BF16(acc[mi][ni], ah[mi], bh[ni]);
                    MMA_BF16(acc[mi][ni], al[mi], bh[ni]);
                }
#pragma unroll
            for (int ni = 0; ni < 6; ni++) {
                uint32_t adb = (uint32_t)__cvta_generic_to_shared(
                    &sWL[(wc * 48 + ni * 8 + b_n) * 40 + k0 + b_k]);
                LDSM_X2(bl[ni], adb);
            }
#pragma unroll
            for (int mi = 0; mi < 4; mi++)
#pragma unroll
                for (int ni = 0; ni < 6; ni++)
                    MMA_BF16(acc[mi][ni], ah[mi], bl[ni]);
        }
    }

    // epilogue: regs -> g_qkv
#pragma unroll
    for (int mi = 0; mi < 4; mi++) {
        int r0 = m0 + wr * 64 + mi * 16 + (lane >> 2);
#pragma unroll
        for (int ni = 0; ni < 6; ni++) {
            int col = wc * 48 + ni * 8 + (lane & 3) * 2;
            *(float2*)&g_qkv[(size_t)r0 * NN + col] =
                make_float2(acc[mi][ni][0], acc[mi][ni][1]);
            *(float2*)&g_qkv[(size_t)(r0 + 8) * NN + col] =
                make_float2(acc[mi][ni][2], acc[mi][ni][3]);
        }
    }
}

// ---------------- Kernel 2: fused score/softmax/value (unchanged) ----------------
template <int SLIM>
__device__ __forceinline__ void attn_body(
    const float* __restrict__ Wql,
    const float* __restrict__ Wkl,
    float* __restrict__ out,
    int b, int tb)
{
    constexpr int US = SLIM + 8;
    constexpr int CW = SLIM / 16;
    extern __shared__ float smem[];
    float* sU = smem;
    float* sW = sU + 64 * US;
    float* sZ = sW + 16 * US;
    float* sV = sZ + 64 * 132;

    const int tid = threadIdx.x;
    const int tr  = tid >> 4;
    const int tc  = tid & 15;
    const int base_row = b * NT + tb * 64;

    for (int L = tid; L < 64 * 32; L += 256) {
        int t = L >> 5, f = L & 31;
        float4 v = *(const float4*)&g_qkv[(size_t)(base_row + t) * NN + f * 4];
        *(float4*)&sZ[t * 132 + f * 4] = v;
    }
    for (int L = tid; L < SLIM * 16; L += 256) {
        int s = L >> 4, f = L & 15;
        float4 v = *(const float4*)&g_qkv[(size_t)(b * NT + s) * NN + 128 + f * 4];
        *(float4*)&sV[s * 72 + f * 4] = v;
    }

    float acc[4][CW];
#pragma unroll
    for (int i = 0; i < 4; i++)
#pragma unroll
        for (int j = 0; j < CW; j++) acc[i][j] = 0.f;

    for (int kt = 0; kt < 8; kt++) {
        const int k0 = kt * 16;
        __syncthreads();
        for (int L = tid; L < 4 * SLIM; L += 256) {
            int kr = L / (SLIM / 4);
            int f  = L % (SLIM / 4);
            int kg = k0 + kr;
            const float* Wp = (kg < 64) ? (Wql + kg * NS) : (Wkl + (kg - 64) * NS);
            float4 v = *(const float4*)&Wp[f * 4];
            *(float4*)&sW[kr * US + f * 4] = v;
        }
        __syncthreads();
#pragma unroll
        for (int kk = 0; kk < 16; kk++) {
            float a[4];
#pragma unroll
            for (int i = 0; i < 4; i++) a[i] = sZ[(tr * 4 + i) * 132 + k0 + kk];
            float bm[CW];
#pragma unroll
            for (int u = 0; u < CW / 4; u++) {
                float4 bv = *(const float4*)&sW[kk * US + tc * CW + u * 4];
                bm[u * 4 + 0] = bv.x; bm[u * 4 + 1] = bv.y;
                bm[u * 4 + 2] = bv.z; bm[u * 4 + 3] = bv.w;
            }
#pragma unroll
            for (int i = 0; i < 4; i++)
#pragma unroll
                for (int j = 0; j < CW; j++)
                    acc[i][j] = fmaf(a[i], bm[j], acc[i][j]);
        }
    }

#pragma unroll
    for (int i = 0; i < 4; i++) {
        int tg = tb * 64 + tr * 4 + i;
#pragma unroll
        for (int j = 0; j < CW; j++) {
            int s = tc * CW + j;
            sU[(tr * 4 + i) * US + s] = (s <= tg) ? tanhf(acc[i][j]) : -1e30f;
        }
    }
    __syncthreads();

    {
        const int warp = tid >> 5, lane = tid & 31;
        constexpr int NITER = SLIM / 32;
        for (int rr = 0; rr < 8; rr++) {
            int row = warp * 8 + rr;
            float vals[NITER];
            float m = -1e30f;
#pragma unroll
            for (int q = 0; q < NITER; q++) {
                vals[q] = sU[row * US + q * 32 + lane];
                m = fmaxf(m, vals[q]);
            }
#pragma unroll
            for (int off = 16; off > 0; off >>= 1)
                m = fmaxf(m, __shfl_xor_sync(0xffffffffu, m, off));
            float ssum = 0.f;
#pragma unroll
            for (int q = 0; q < NITER; q++) { vals[q] = __expf(vals[q] - m); ssum += vals[q]; }
#pragma unroll
            for (int off = 16; off > 0; off >>= 1)
                ssum += __shfl_xor_sync(0xffffffffu, ssum, off);
            float inv = 1.f / ssum;
#pragma unroll
            for (int q = 0; q < NITER; q++)
                sU[row * US + q * 32 + lane] = vals[q] * inv;
        }
    }
    __syncthreads();

    float acc2[4][4];
#pragma unroll
    for (int i = 0; i < 4; i++)
#pragma unroll
        for (int j = 0; j < 4; j++) acc2[i][j] = 0.f;

    for (int s = 0; s < SLIM; s += 4) {
        float4 af[4];
#pragma unroll
        for (int i = 0; i < 4; i++)
            af[i] = *(const float4*)&sU[(tr * 4 + i) * US + s];
#pragma unroll
        for (int ss = 0; ss < 4; ss++) {
            float4 bv = *(const float4*)&sV[(s + ss) * 72 + tc * 4];
#pragma unroll
            for (int i = 0; i < 4; i++) {
                float a = ((const float*)&af[i])[ss];
                acc2[i][0] = fmaf(a, bv.x, acc2[i][0]);
                acc2[i][1] = fmaf(a, bv.y, acc2[i][1]);
                acc2[i][2] = fmaf(a, bv.z, acc2[i][2]);
                acc2[i][3] = fmaf(a, bv.w, acc2[i][3]);
            }
        }
    }
#pragma unroll
    for (int i = 0; i < 4; i++) {
        int tg = tb * 64 + tr * 4 + i;
        *(float4*)&out[(size_t)(b * NT + tg) * NH + tc * 4] =
            make_float4(acc2[i][0], acc2[i][1], acc2[i][2], acc2[i][3]);
    }
}

__global__ __launch_bounds__(256) void attn_kernel(
    const float* __restrict__ Wql,
    const float* __restrict__ Wkl,
    float* __restrict__ out)
{
    const int tb = blockIdx.x;
    const int b  = blockIdx.y;
    if (tb == 0)      attn_body<64 >(Wql, Wkl, out, b, 0);
    else if (tb == 1) attn_body<128>(Wql, Wkl, out, b, 1);
    else if (tb == 2) attn_body<192>(Wql, Wkl, out, b, 2);
    else              attn_body<256>(Wql, Wkl, out, b, 3);
}

#define ATTN_SMEM_BYTES 192000

extern "C" void kernel_launch(void* const* d_in, const int* in_sizes, int n_in,
                              void* d_out, int out_size)
{
    (void)in_sizes; (void)n_in; (void)out_size;
    const float* x   = (const float*)d_in[0];
    const float* Wq  = (const float*)d_in[1];
    const float* Wk  = (const float*)d_in[2];
    const float* Wv  = (const float*)d_in[3];
    const float* Wql = (const float*)d_in[4];
    const float* Wkl = (const float*)d_in[5];
    float* out = (float*)d_out;

    cudaFuncSetAttribute((const void*)attn_kernel,
                         cudaFuncAttributeMaxDynamicSharedMemorySize, ATTN_SMEM_BYTES);
    cudaFuncSetAttribute((const void*)qkv_mma_kernel,
                         cudaFuncAttributeMaxDynamicSharedMemorySize, QKV_SMEM_BYTES);

    convert_w_kernel<<<(NN * NC + 255) / 256, 256>>>(Wq, Wk, Wv);
    qkv_mma_kernel<<<NM / 128, 256, QKV_SMEM_BYTES>>>(x);

    dim3 grid(4, NB);
    attn_kernel<<<grid, 256, ATTN_SMEM_BYTES>>>(Wql, Wkl, out);
}

// round 4
// speedup vs baseline: 2.4177x; 1.8286x over previous
#include <cuda_runtime.h>
#include <cuda_bf16.h>
#include <math.h>
#include <stdint.h>

#define NB 512
#define NT 256
#define NC 384
#define NH 64
#define NS 256
#define NM (NB*NT)   // 131072 rows
#define NN 192       // q|k|v fused output cols

// scratch (device globals: allocation-guard safe)
__device__ __align__(16) float         g_qkv[NM * NN]; // per row: [0:64)=q [64:128)=k [128:192)=v
__device__ __align__(16) __nv_bfloat16 g_wh[NN * NC];  // qkv W  [n][k] K-major split
__device__ __align__(16) __nv_bfloat16 g_wl[NN * NC];
__device__ __align__(16) __nv_bfloat16 g_wch[128 * 256]; // Wcat [k][s] split (k<64: Wql, else Wkl)
__device__ __align__(16) __nv_bfloat16 g_wcl[128 * 256];

// ---------------- W split-bf16 conversion (tiny) ----------------
__global__ __launch_bounds__(256) void convert_w_kernel(
    const float* __restrict__ Wq, const float* __restrict__ Wk, const float* __restrict__ Wv,
    const float* __restrict__ Wql, const float* __restrict__ Wkl)
{
    const int idx = blockIdx.x * 256 + threadIdx.x;
    if (idx < NN * NC) {
        const int n = idx / NC, k = idx % NC;
        const float* W = (n < 64) ? Wq : (n < 128) ? Wk : Wv;
        float v = W[k * NH + (n & 63)];
        __nv_bfloat16 h = __float2bfloat16(v);
        g_wh[idx] = h;
        g_wl[idx] = __float2bfloat16(v - __bfloat162float(h));
    }
    const int idx2 = idx - NN * NC;
    if (idx2 >= 0 && idx2 < 128 * 256) {
        const int k = idx2 >> 8, s = idx2 & 255;
        float v = (k < 64) ? Wql[k * NS + s] : Wkl[(k - 64) * NS + s];
        __nv_bfloat16 h = __float2bfloat16(v);
        g_wch[idx2] = h;
        g_wcl[idx2] = __float2bfloat16(v - __bfloat162float(h));
    }
}

// ---------------- mma.sync helpers (baseline PTX ISA) ----------------
#define LDSM_X4(r, addr)                                                        \
    asm volatile("ldmatrix.sync.aligned.m8n8.x4.shared.b16 {%0,%1,%2,%3}, [%4];" \
        : "=r"((r)[0]), "=r"((r)[1]), "=r"((r)[2]), "=r"((r)[3]) : "r"(addr))

#define LDSM_X2(r, addr)                                                        \
    asm volatile("ldmatrix.sync.aligned.m8n8.x2.shared.b16 {%0,%1}, [%2];"      \
        : "=r"((r)[0]), "=r"((r)[1]) : "r"(addr))

#define LDSM_X2_T(r, addr)                                                      \
    asm volatile("ldmatrix.sync.aligned.m8n8.x2.trans.shared.b16 {%0,%1}, [%2];" \
        : "=r"((r)[0]), "=r"((r)[1]) : "r"(addr))

#define MMA_BF16(d, a, b)                                                       \
    asm volatile("mma.sync.aligned.m16n8k16.row.col.f32.bf16.bf16.f32 "         \
        "{%0,%1,%2,%3}, {%4,%5,%6,%7}, {%8,%9}, {%0,%1,%2,%3};"                 \
        : "+f"((d)[0]), "+f"((d)[1]), "+f"((d)[2]), "+f"((d)[3])                \
        : "r"((a)[0]), "r"((a)[1]), "r"((a)[2]), "r"((a)[3]),                   \
          "r"((b)[0]), "r"((b)[1]))

static __device__ __forceinline__ uint32_t pack_bf2(float a, float b) {
    __nv_bfloat162 t = __floats2bfloat162_rn(a, b);
    return *(uint32_t*)&t;
}

// ---------------- Kernel 1: split-bf16 QKV GEMM via mma.sync (unchanged) ----------------
#define QKV_SMEM_BYTES ((5120 + 5120 + 7680 + 7680) * 2)

__global__ __launch_bounds__(256) void qkv_mma_kernel(const float* __restrict__ x)
{
    extern __shared__ __nv_bfloat16 sm[];
    __nv_bfloat16* sXH = sm;
    __nv_bfloat16* sXL = sm + 5120;
    __nv_bfloat16* sWH = sm + 10240;
    __nv_bfloat16* sWL = sm + 17920;

    const int tid  = threadIdx.x;
    const int lane = tid & 31;
    const int w    = tid >> 5;
    const int wr   = w >> 2;
    const int wc   = w & 3;
    const int m0   = blockIdx.x * 128;

    float acc[4][6][4];
#pragma unroll
    for (int mi = 0; mi < 4; mi++)
#pragma unroll
        for (int ni = 0; ni < 6; ni++)
#pragma unroll
            for (int q = 0; q < 4; q++) acc[mi][ni][q] = 0.f;

    const int a_row = (lane & 7) + ((lane >> 3) & 1) * 8;
    const int a_col = (lane >> 4) * 8;
    const int b_n   = lane & 7;
    const int b_k   = ((lane >> 3) & 1) * 8;

    for (int c = 0; c < 12; c++) {
        const int kc = c * 32;
        __syncthreads();

#pragma unroll
        for (int i = 0; i < 4; i++) {
            int idx = tid + 256 * i;
            int row = idx >> 3, seg = idx & 7;
            float4 v = *(const float4*)&x[(size_t)(m0 + row) * NC + kc + seg * 4];
            float vv[4] = {v.x, v.y, v.z, v.w};
            __nv_bfloat16 h[4], l[4];
#pragma unroll
            for (int j = 0; j < 4; j++) {
                h[j] = __float2bfloat16(vv[j]);
                l[j] = __float2bfloat16(vv[j] - __bfloat162float(h[j]));
            }
            *(uint2*)&sXH[row * 40 + seg * 4] = *(uint2*)h;
            *(uint2*)&sXL[row * 40 + seg * 4] = *(uint2*)l;
        }
#pragma unroll
        for (int i = 0; i < 3; i++) {
            int idx = tid + 256 * i;
            int row = idx >> 2, seg = idx & 3;
            *(uint4*)&sWH[row * 40 + seg * 8] =
                *(const uint4*)&g_wh[(size_t)row * NC + kc + seg * 8];
            *(uint4*)&sWL[row * 40 + seg * 8] =
                *(const uint4*)&g_wl[(size_t)row * NC + kc + seg * 8];
        }
        __syncthreads();

#pragma unroll
        for (int kk = 0; kk < 2; kk++) {
            const int k0 = kk * 16;
            uint32_t ah[4][4], al[4][4], bh[6][2], bl[6][2];
#pragma unroll
            for (int mi = 0; mi < 4; mi++) {
                uint32_t adh = (uint32_t)__cvta_generic_to_shared(
                    &sXH[(wr * 64 + mi * 16 + a_row) * 40 + k0 + a_col]);
                LDSM_X4(ah[mi], adh);
                uint32_t adl = (uint32_t)__cvta_generic_to_shared(
                    &sXL[(wr * 64 + mi * 16 + a_row) * 40 + k0 + a_col]);
                LDSM_X4(al[mi], adl);
            }
#pragma unroll
            for (int ni = 0; ni < 6; ni++) {
                uint32_t adb = (uint32_t)__cvta_generic_to_shared(
                    &sWH[(wc * 48 + ni * 8 + b_n) * 40 + k0 + b_k]);
                LDSM_X2(bh[ni], adb);
            }
#pragma unroll
            for (int mi = 0; mi < 4; mi++)
#pragma unroll
                for (int ni = 0; ni < 6; ni++) {
                    MMA_BF16(acc[mi][ni], ah[mi], bh[ni]);
                    MMA_BF16(acc[mi][ni], al[mi], bh[ni]);
                }
#pragma unroll
            for (int ni = 0; ni < 6; ni++) {
                uint32_t adb = (uint32_t)__cvta_generic_to_shared(
                    &sWL[(wc * 48 + ni * 8 + b_n) * 40 + k0 + b_k]);
                LDSM_X2(bl[ni], adb);
            }
#pragma unroll
            for (int mi = 0; mi < 4; mi++)
#pragma unroll
                for (int ni = 0; ni < 6; ni++)
                    MMA_BF16(acc[mi][ni], ah[mi], bl[ni]);
        }
    }

#pragma unroll
    for (int mi = 0; mi < 4; mi++) {
        int r0 = m0 + wr * 64 + mi * 16 + (lane >> 2);
#pragma unroll
        for (int ni = 0; ni < 6; ni++) {
            int col = wc * 48 + ni * 8 + (lane & 3) * 2;
            *(float2*)&g_qkv[(size_t)r0 * NN + col] =
                make_float2(acc[mi][ni][0], acc[mi][ni][1]);
            *(float2*)&g_qkv[(size_t)(r0 + 8) * NN + col] =
                make_float2(acc[mi][ni][2], acc[mi][ni][3]);
        }
    }
}

// ---------------- Kernel 2: flash-style attn via mma.sync ----------------
// Per block (b, tb): 64 t-rows, SLIM = (tb+1)*64 s-cols.
// GEMM1: u[64][SLIM] = z[64][128] @ Wcat[128][SLIM]  (split-bf16, 3 terms)
// p = exp(tanh(u)) masked (no max needed: tanh bounded); row-normalize.
// GEMM2: out[64][64] = p[64][SLIM] @ v[SLIM][64]     (split-bf16, 3 terms)
// 8 warps: 4 in m (16 rows each) x 2 in n/k (SLIM/2 each).

template <int SLIM>
__device__ __forceinline__ void attn_body(float* __restrict__ out, int b, int tb)
{
    constexpr int SLIMP = SLIM + 8;    // bf16 stride for W chunk
    constexpr int NTW   = SLIM / 16;   // GEMM1 n8-tiles per warp (per n-half)
    constexpr int KW    = SLIM / 2;    // warp k-range in GEMM2

    extern __shared__ char smraw[];
    __nv_bfloat16* sZH = (__nv_bfloat16*)smraw;          // [64][136]
    __nv_bfloat16* sZL = sZH + 64 * 136;
    __nv_bfloat16* sVH = sZL + 64 * 136;                 // [SLIM][72]
    __nv_bfloat16* sVL = sVH + SLIM * 72;
    __nv_bfloat16* sWH = sVL + SLIM * 72;                // [2][16][SLIMP]
    __nv_bfloat16* sWL = sWH + 2 * 16 * SLIMP;
    float* rowsumS     = (float*)(sWL + 2 * 16 * SLIMP); // [2][64]
    float* sOut        = (float*)sWH;                    // [64][72], reused after GEMM1

    const int tid  = threadIdx.x;
    const int lane = tid & 31;
    const int w    = tid >> 5;
    const int wm   = w >> 1;    // 0..3 : rows wm*16
    const int wn   = w & 1;     // 0..1 : n/k half

    const int a_row = (lane & 7) + ((lane >> 3) & 1) * 8;
    const int a_col = (lane >> 4) * 8;
    const int l16   = lane & 15;
    const int qr    = lane >> 2;       // quad row 0..7
    const int qc    = (lane & 3) * 2;  // quad col pair

    const int base_row = b * NT + tb * 64;

    // ---- stage z (64x128 f32 -> split bf16) ----
#pragma unroll
    for (int L = tid; L < 64 * 32; L += 256) {
        int t = L >> 5, f = L & 31;
        float4 v = *(const float4*)&g_qkv[(size_t)(base_row + t) * NN + f * 4];
        float vv[4] = {v.x, v.y, v.z, v.w};
        __nv_bfloat16 h[4], l[4];
#pragma unroll
        for (int j = 0; j < 4; j++) {
            h[j] = __float2bfloat16(vv[j]);
            l[j] = __float2bfloat16(vv[j] - __bfloat162float(h[j]));
        }
        *(uint2*)&sZH[t * 136 + f * 4] = *(uint2*)h;
        *(uint2*)&sZL[t * 136 + f * 4] = *(uint2*)l;
    }
    // ---- stage v (SLIMx64 f32 -> split bf16) ----
#pragma unroll
    for (int L = tid; L < SLIM * 16; L += 256) {
        int s = L >> 4, f = L & 15;
        float4 v = *(const float4*)&g_qkv[(size_t)(b * NT + s) * NN + 128 + f * 4];
        float vv[4] = {v.x, v.y, v.z, v.w};
        __nv_bfloat16 h[4], l[4];
#pragma unroll
        for (int j = 0; j < 4; j++) {
            h[j] = __float2bfloat16(vv[j]);
            l[j] = __float2bfloat16(vv[j] - __bfloat162float(h[j]));
        }
        *(uint2*)&sVH[s * 72 + f * 4] = *(uint2*)h;
        *(uint2*)&sVL[s * 72 + f * 4] = *(uint2*)l;
    }

    // ---- W chunk staging helper: rows [ks*16, ks*16+16) of Wcat, cols [0,SLIM) ----
    auto stageW = [&](int ks, int buf) {
#pragma unroll
        for (int u = tid; u < 2 * SLIM; u += 256) {
            int r  = u / (SLIM / 8);
            int cs = u % (SLIM / 8);
            *(uint4*)&sWH[(buf * 16 + r) * SLIMP + cs * 8] =
                *(const uint4*)&g_wch[(ks * 16 + r) * 256 + cs * 8];
            *(uint4*)&sWL[(buf * 16 + r) * SLIMP + cs * 8] =
                *(const uint4*)&g_wcl[(ks * 16 + r) * 256 + cs * 8];
        }
    };

    stageW(0, 0);
    __syncthreads();

    // ---- GEMM1 ----
    float acc[NTW][4];
#pragma unroll
    for (int j = 0; j < NTW; j++)
#pragma unroll
        for (int q = 0; q < 4; q++) acc[j][q] = 0.f;

    for (int ks = 0; ks < 8; ks++) {
        const int buf = ks & 1;
        if (ks < 7) stageW(ks + 1, buf ^ 1);

        uint32_t ah[4], al[4];
        {
            uint32_t ad = (uint32_t)__cvta_generic_to_shared(
                &sZH[(wm * 16 + a_row) * 136 + ks * 16 + a_col]);
            LDSM_X4(ah, ad);
            ad = (uint32_t)__cvta_generic_to_shared(
                &sZL[(wm * 16 + a_row) * 136 + ks * 16 + a_col]);
            LDSM_X4(al, ad);
        }
#pragma unroll
        for (int j = 0; j < NTW; j++) {
            const int n0 = wn * KW + j * 8;
            uint32_t bh[2], bl[2];
            uint32_t ad = (uint32_t)__cvta_generic_to_shared(
                &sWH[(buf * 16 + l16) * SLIMP + n0]);
            LDSM_X2_T(bh, ad);
            ad = (uint32_t)__cvta_generic_to_shared(
                &sWL[(buf * 16 + l16) * SLIMP + n0]);
            LDSM_X2_T(bl, ad);
            MMA_BF16(acc[j], ah, bh);
            MMA_BF16(acc[j], al, bh);
            MMA_BF16(acc[j], ah, bl);
        }
        __syncthreads();
    }

    // ---- tanh + mask + exp + row sums ----
    const int tg0 = tb * 64 + wm * 16 + qr;   // global t for row qr
    float rsum0 = 0.f, rsum1 = 0.f;
#pragma unroll
    for (int j = 0; j < NTW; j++) {
        const int c0 = wn * KW + j * 8 + qc;  // absolute s of elem 0
        float v0 = (c0     <= tg0    ) ? __expf(tanhf(acc[j][0])) : 0.f;
        float v1 = (c0 + 1 <= tg0    ) ? __expf(tanhf(acc[j][1])) : 0.f;
        float v2 = (c0     <= tg0 + 8) ? __expf(tanhf(acc[j][2])) : 0.f;
        float v3 = (c0 + 1 <= tg0 + 8) ? __expf(tanhf(acc[j][3])) : 0.f;
        acc[j][0] = v0; acc[j][1] = v1; acc[j][2] = v2; acc[j][3] = v3;
        rsum0 += v0 + v1;
        rsum1 += v2 + v3;
    }
#pragma unroll
    for (int off = 1; off <= 2; off <<= 1) {
        rsum0 += __shfl_xor_sync(0xffffffffu, rsum0, off);
        rsum1 += __shfl_xor_sync(0xffffffffu, rsum1, off);
    }
    if ((lane & 3) == 0) {
        rowsumS[wn * 64 + wm * 16 + qr]     = rsum0;
        rowsumS[wn * 64 + wm * 16 + qr + 8] = rsum1;
    }
    __syncthreads();
    const float inv0 = 1.f / (rowsumS[wm * 16 + qr]     + rowsumS[64 + wm * 16 + qr]);
    const float inv1 = 1.f / (rowsumS[wm * 16 + qr + 8] + rowsumS[64 + wm * 16 + qr + 8]);

    // ---- GEMM2: out += p @ v, warp covers k in [wn*KW, wn*KW+KW) ----
    float acc2[8][4];
#pragma unroll
    for (int jo = 0; jo < 8; jo++)
#pragma unroll
        for (int q = 0; q < 4; q++) acc2[jo][q] = 0.f;

#pragma unroll
    for (int jp = 0; jp < NTW / 2; jp++) {
        // build A frags (ph, pl) from C tiles 2jp, 2jp+1
        float c00 = acc[2*jp][0]   * inv0, c01 = acc[2*jp][1]   * inv0;
        float c02 = acc[2*jp][2]   * inv1, c03 = acc[2*jp][3]   * inv1;
        float c10 = acc[2*jp+1][0] * inv0, c11 = acc[2*jp+1][1] * inv0;
        float c12 = acc[2*jp+1][2] * inv1, c13 = acc[2*jp+1][3] * inv1;

        uint32_t pa_h[4], pa_l[4];
        pa_h[0] = pack_bf2(c00, c01);
        pa_h[1] = pack_bf2(c02, c03);
        pa_h[2] = pack_bf2(c10, c11);
        pa_h[3] = pack_bf2(c12, c13);
        {
            __nv_bfloat162 t0 = *(__nv_bfloat162*)&pa_h[0];
            __nv_bfloat162 t1 = *(__nv_bfloat162*)&pa_h[1];
            __nv_bfloat162 t2 = *(__nv_bfloat162*)&pa_h[2];
            __nv_bfloat162 t3 = *(__nv_bfloat162*)&pa_h[3];
            pa_l[0] = pack_bf2(c00 - __low2float(t0), c01 - __high2float(t0));
            pa_l[1] = pack_bf2(c02 - __low2float(t1), c03 - __high2float(t1));
            pa_l[2] = pack_bf2(c10 - __low2float(t2), c11 - __high2float(t2));
            pa_l[3] = pack_bf2(c12 - __low2float(t3), c13 - __high2float(t3));
        }

        const int k0 = wn * KW + jp * 16;
#pragma unroll
        for (int jo = 0; jo < 8; jo++) {
            uint32_t bh[2], bl[2];
            uint32_t ad = (uint32_t)__cvta_generic_to_shared(
                &sVH[(k0 + l16) * 72 + jo * 8]);
            LDSM_X2_T(bh, ad);
            ad = (uint32_t)__cvta_generic_to_shared(
                &sVL[(k0 + l16) * 72 + jo * 8]);
            LDSM_X2_T(bl, ad);
            MMA_BF16(acc2[jo], pa_h, bh);
            MMA_BF16(acc2[jo], pa_l, bh);
            MMA_BF16(acc2[jo], pa_h, bl);
        }
    }

    // ---- cross-warp k-reduction (wn pairs) + store ----
    __syncthreads();   // everyone past sW reads (GEMM1 done long ago); safe to reuse as sOut
    if (wn == 0) {
#pragma unroll
        for (int jo = 0; jo < 8; jo++) {
            *(float2*)&sOut[(wm * 16 + qr)     * 72 + jo * 8 + qc] =
                make_float2(acc2[jo][0], acc2[jo][1]);
            *(float2*)&sOut[(wm * 16 + qr + 8) * 72 + jo * 8 + qc] =
                make_float2(acc2[jo][2], acc2[jo][3]);
        }
    }
    __syncthreads();
    if (wn == 1) {
        const int trow0 = base_row + wm * 16 + qr;
#pragma unroll
        for (int jo = 0; jo < 8; jo++) {
            float2 p0 = *(float2*)&sOut[(wm * 16 + qr)     * 72 + jo * 8 + qc];
            float2 p1 = *(float2*)&sOut[(wm * 16 + qr + 8) * 72 + jo * 8 + qc];
            *(float2*)&out[(size_t)trow0 * NH + jo * 8 + qc] =
                make_float2(acc2[jo][0] + p0.x, acc2[jo][1] + p0.y);
            *(float2*)&out[(size_t)(trow0 + 8) * NH + jo * 8 + qc] =
                make_float2(acc2[jo][2] + p1.x, acc2[jo][3] + p1.y);
        }
    }
}

__global__ __launch_bounds__(256) void attn_kernel(float* __restrict__ out)
{
    const int tb = blockIdx.x;
    const int b  = blockIdx.y;
    if (tb == 0)      attn_body<64 >(out, b, 0);
    else if (tb == 1) attn_body<128>(out, b, 1);
    else if (tb == 2) attn_body<192>(out, b, 2);
    else              attn_body<256>(out, b, 3);
}

// smem for SLIM=256: 2*64*136*2 + 2*256*72*2 + 2*(2*16*264*2) + 512 = 142848
#define ATTN_SMEM_BYTES 142848

extern "C" void kernel_launch(void* const* d_in, const int* in_sizes, int n_in,
                              void* d_out, int out_size)
{
    (void)in_sizes; (void)n_in; (void)out_size;
    const float* x   = (const float*)d_in[0];
    const float* Wq  = (const float*)d_in[1];
    const float* Wk  = (const float*)d_in[2];
    const float* Wv  = (const float*)d_in[3];
    const float* Wql = (const float*)d_in[4];
    const float* Wkl = (const float*)d_in[5];
    float* out = (float*)d_out;

    cudaFuncSetAttribute((const void*)attn_kernel,
                         cudaFuncAttributeMaxDynamicSharedMemorySize, ATTN_SMEM_BYTES);
    cudaFuncSetAttribute((const void*)qkv_mma_kernel,
                         cudaFuncAttributeMaxDynamicSharedMemorySize, QKV_SMEM_BYTES);

    const int conv_total = NN * NC + 128 * 256;
    convert_w_kernel<<<(conv_total + 255) / 256, 256>>>(Wq, Wk, Wv, Wql, Wkl);
    qkv_mma_kernel<<<NM / 128, 256, QKV_SMEM_BYTES>>>(x);

    dim3 grid(4, NB);
    attn_kernel<<<grid, 256, ATTN_SMEM_BYTES>>>(out);
}